// round 2
// baseline (speedup 1.0000x reference)
#include <cuda_runtime.h>
#include <cuda_bf16.h>

// YOLO loss: streaming HBM-bound reduction.
// Pass 1: per-block staged loads (float4, fully coalesced) -> smem ->
//         per-cell branchless loss -> warp+block reduce -> g_partials.
// Pass 2: single block reduces g_partials in double, writes 4 outputs.

#define NUM_CLASSES 10
#define PP 15                 // 5 + NUM_CLASSES floats per cell
#define CPB 256               // cells per block
#define THREADS 256
#define SMEM_FLOATS (CPB * PP)   // 3840 floats per array

#define MAX_BLOCKS 8192
__device__ float g_partials[MAX_BLOCKS * 3];

__global__ __launch_bounds__(THREADS)
void yolo_loss_kernel(const float* __restrict__ pred,
                      const float* __restrict__ tgt,
                      long long n_floats, int n_cells)
{
    __shared__ float s_pred[SMEM_FLOATS];
    __shared__ float s_tgt[SMEM_FLOATS];
    __shared__ float s_red[3][8];

    const int tid = threadIdx.x;
    const long long base = (long long)blockIdx.x * SMEM_FLOATS;

    // ---- staged coalesced loads (float4) ----
    {
        const float4* gp = reinterpret_cast<const float4*>(pred + base);
        const float4* gt = reinterpret_cast<const float4*>(tgt + base);
        float4* sp4 = reinterpret_cast<float4*>(s_pred);
        float4* st4 = reinterpret_cast<float4*>(s_tgt);
        const long long n4 = (n_floats - base) / 4;   // remaining float4s
        #pragma unroll
        for (int i = tid; i < SMEM_FLOATS / 4; i += THREADS) {
            if ((long long)i < n4) {
                sp4[i] = gp[i];
                st4[i] = gt[i];
            }
        }
    }
    __syncthreads();

    // ---- per-cell loss (1 cell / thread; smem stride 15 -> conflict-free) ----
    float coord = 0.f, conf = 0.f, cls = 0.f;
    {
        const int cell_global = blockIdx.x * CPB + tid;
        if (cell_global < n_cells) {
            const float* p = s_pred + tid * PP;
            const float* t = s_tgt  + tid * PP;

            const float t4 = t[4];
            const float obj = (t4 > 0.f) ? 1.f : 0.f;

            float cs = 0.f;
            #pragma unroll
            for (int i = 0; i < 4; i++) { float d = p[i] - t[i]; cs += d * d; }

            const float sg = 1.f / (1.f + __expf(-p[4]));
            const float dconf = sg - t4;

            float ks = 0.f;
            #pragma unroll
            for (int i = 5; i < 15; i++) { float d = p[i] - t[i]; ks += d * d; }

            coord = obj * cs;
            conf  = obj * (dconf * dconf) + (1.f - obj) * 0.5f * sg * sg;
            cls   = obj * ks;
        }
    }

    // ---- warp reduce ----
    #pragma unroll
    for (int off = 16; off > 0; off >>= 1) {
        coord += __shfl_down_sync(0xFFFFFFFFu, coord, off);
        conf  += __shfl_down_sync(0xFFFFFFFFu, conf,  off);
        cls   += __shfl_down_sync(0xFFFFFFFFu, cls,   off);
    }
    const int wid  = tid >> 5;
    const int lane = tid & 31;
    if (lane == 0) {
        s_red[0][wid] = coord;
        s_red[1][wid] = conf;
        s_red[2][wid] = cls;
    }
    __syncthreads();

    if (tid == 0) {
        float c0 = 0.f, c1 = 0.f, c2 = 0.f;
        #pragma unroll
        for (int w = 0; w < THREADS / 32; w++) {
            c0 += s_red[0][w]; c1 += s_red[1][w]; c2 += s_red[2][w];
        }
        g_partials[blockIdx.x * 3 + 0] = c0;
        g_partials[blockIdx.x * 3 + 1] = c1;
        g_partials[blockIdx.x * 3 + 2] = c2;
    }
}

__global__ __launch_bounds__(256)
void yolo_finalize_kernel(int nblocks, float* __restrict__ out)
{
    __shared__ double s_red[3][8];
    const int tid = threadIdx.x;

    double c = 0.0, f = 0.0, k = 0.0;
    for (int i = tid; i < nblocks; i += 256) {
        c += (double)g_partials[i * 3 + 0];
        f += (double)g_partials[i * 3 + 1];
        k += (double)g_partials[i * 3 + 2];
    }
    #pragma unroll
    for (int off = 16; off > 0; off >>= 1) {
        c += __shfl_down_sync(0xFFFFFFFFu, c, off);
        f += __shfl_down_sync(0xFFFFFFFFu, f, off);
        k += __shfl_down_sync(0xFFFFFFFFu, k, off);
    }
    const int wid  = tid >> 5;
    const int lane = tid & 31;
    if (lane == 0) { s_red[0][wid] = c; s_red[1][wid] = f; s_red[2][wid] = k; }
    __syncthreads();

    if (tid == 0) {
        double tc = 0.0, tf = 0.0, tk = 0.0;
        #pragma unroll
        for (int w = 0; w < 8; w++) { tc += s_red[0][w]; tf += s_red[1][w]; tk += s_red[2][w]; }
        const float coord_loss = (float)(5.0 * tc);          // LAMBDA_COORD
        const float conf_loss  = (float)tf;
        const float class_loss = (float)(tk * (1.0 / NUM_CLASSES)); // mean over C
        out[0] = coord_loss + conf_loss + class_loss;
        out[1] = coord_loss;
        out[2] = conf_loss;
        out[3] = class_loss;
    }
}

extern "C" void kernel_launch(void* const* d_in, const int* in_sizes, int n_in,
                              void* d_out, int out_size)
{
    const float* pred = (const float*)d_in[0];
    const float* tgt  = (const float*)d_in[1];
    float* out = (float*)d_out;

    const long long n_floats = (long long)in_sizes[0];
    const int n_cells = (int)(n_floats / PP);
    const int nblocks = (n_cells + CPB - 1) / CPB;   // 5408 for the given shape

    yolo_loss_kernel<<<nblocks, THREADS>>>(pred, tgt, n_floats, n_cells);
    yolo_finalize_kernel<<<1, 256>>>(nblocks, out);
}

// round 4
// speedup vs baseline: 1.2315x; 1.2315x over previous
#include <cuda_runtime.h>
#include <cuda_bf16.h>

// YOLO loss: single-kernel streaming HBM-bound reduction.
// Each block: staged coalesced float4 loads -> smem -> per-cell branchless
// loss -> warp+block reduce -> partials. Last block to finish (ticket via
// atomic counter) reduces all partials and writes the 4 outputs.
// Deterministic: the final reduction reads fixed slots in a fixed order.

#define NUM_CLASSES 10
#define PP 15                 // 5 + NUM_CLASSES floats per cell
#define CPB 256               // cells per block
#define THREADS 256
#define SMEM_FLOATS (CPB * PP)   // 3840 floats per array

#define MAX_BLOCKS 8192
__device__ float4 g_partials[MAX_BLOCKS];    // x=coord, y=conf, z=cls, w=pad
__device__ unsigned int g_ticket;            // zero-init; reset by last block

__global__ __launch_bounds__(THREADS)
void yolo_loss_kernel(const float* __restrict__ pred,
                      const float* __restrict__ tgt,
                      long long n_floats, int n_cells,
                      float* __restrict__ out)
{
    __shared__ float s_pred[SMEM_FLOATS];
    __shared__ float s_tgt[SMEM_FLOATS];
    __shared__ float s_red[3][8];
    __shared__ bool  s_is_last;

    const int tid = threadIdx.x;
    const long long base = (long long)blockIdx.x * SMEM_FLOATS;

    // ---- staged coalesced loads (float4) ----
    {
        const float4* gp = reinterpret_cast<const float4*>(pred + base);
        const float4* gt = reinterpret_cast<const float4*>(tgt + base);
        float4* sp4 = reinterpret_cast<float4*>(s_pred);
        float4* st4 = reinterpret_cast<float4*>(s_tgt);
        const long long n4 = (n_floats - base) / 4;   // remaining float4s
        #pragma unroll
        for (int i = tid; i < SMEM_FLOATS / 4; i += THREADS) {
            if ((long long)i < n4) {
                sp4[i] = gp[i];
                st4[i] = gt[i];
            }
        }
    }
    __syncthreads();

    // ---- per-cell loss (1 cell / thread; smem stride 15 -> conflict-free) ----
    float coord = 0.f, conf = 0.f, cls = 0.f;
    {
        const int cell_global = blockIdx.x * CPB + tid;
        if (cell_global < n_cells) {
            const float* p = s_pred + tid * PP;
            const float* t = s_tgt  + tid * PP;

            const float t4 = t[4];
            const float obj = (t4 > 0.f) ? 1.f : 0.f;

            float cs = 0.f;
            #pragma unroll
            for (int i = 0; i < 4; i++) { float d = p[i] - t[i]; cs += d * d; }

            const float sg = 1.f / (1.f + __expf(-p[4]));
            const float dconf = sg - t4;

            float ks = 0.f;
            #pragma unroll
            for (int i = 5; i < 15; i++) { float d = p[i] - t[i]; ks += d * d; }

            coord = obj * cs;
            conf  = obj * (dconf * dconf) + (1.f - obj) * 0.5f * sg * sg;
            cls   = obj * ks;
        }
    }

    // ---- warp reduce ----
    #pragma unroll
    for (int off = 16; off > 0; off >>= 1) {
        coord += __shfl_down_sync(0xFFFFFFFFu, coord, off);
        conf  += __shfl_down_sync(0xFFFFFFFFu, conf,  off);
        cls   += __shfl_down_sync(0xFFFFFFFFu, cls,   off);
    }
    const int wid  = tid >> 5;
    const int lane = tid & 31;
    if (lane == 0) {
        s_red[0][wid] = coord;
        s_red[1][wid] = conf;
        s_red[2][wid] = cls;
    }
    __syncthreads();

    if (tid == 0) {
        float c0 = 0.f, c1 = 0.f, c2 = 0.f;
        #pragma unroll
        for (int w = 0; w < THREADS / 32; w++) {
            c0 += s_red[0][w]; c1 += s_red[1][w]; c2 += s_red[2][w];
        }
        g_partials[blockIdx.x] = make_float4(c0, c1, c2, 0.f);
        __threadfence();
        unsigned int ticket = atomicAdd(&g_ticket, 1u);
        s_is_last = (ticket == gridDim.x - 1);
    }
    __syncthreads();

    // ---- last block: final reduction over all partials (L2-warm) ----
    if (s_is_last) {
        const int nblocks = gridDim.x;
        float c = 0.f, f = 0.f, k = 0.f;
        for (int i = tid; i < nblocks; i += THREADS) {
            const float4 v = g_partials[i];
            c += v.x; f += v.y; k += v.z;
        }
        #pragma unroll
        for (int off = 16; off > 0; off >>= 1) {
            c += __shfl_down_sync(0xFFFFFFFFu, c, off);
            f += __shfl_down_sync(0xFFFFFFFFu, f, off);
            k += __shfl_down_sync(0xFFFFFFFFu, k, off);
        }
        __syncthreads();   // reuse s_red safely
        if (lane == 0) { s_red[0][wid] = c; s_red[1][wid] = f; s_red[2][wid] = k; }
        __syncthreads();

        if (tid == 0) {
            double tc = 0.0, tf = 0.0, tk = 0.0;
            #pragma unroll
            for (int w = 0; w < THREADS / 32; w++) {
                tc += (double)s_red[0][w];
                tf += (double)s_red[1][w];
                tk += (double)s_red[2][w];
            }
            const float coord_loss = (float)(5.0 * tc);                 // LAMBDA_COORD
            const float conf_loss  = (float)tf;
            const float class_loss = (float)(tk * (1.0 / NUM_CLASSES)); // mean over C
            out[0] = coord_loss + conf_loss + class_loss;
            out[1] = coord_loss;
            out[2] = conf_loss;
            out[3] = class_loss;
            g_ticket = 0;   // reset for next graph replay
        }
    }
}

extern "C" void kernel_launch(void* const* d_in, const int* in_sizes, int n_in,
                              void* d_out, int out_size)
{
    const float* pred = (const float*)d_in[0];
    const float* tgt  = (const float*)d_in[1];
    float* out = (float*)d_out;

    const long long n_floats = (long long)in_sizes[0];
    const int n_cells = (int)(n_floats / PP);
    const int nblocks = (n_cells + CPB - 1) / CPB;   // 5408 for the given shape

    yolo_loss_kernel<<<nblocks, THREADS>>>(pred, tgt, n_floats, n_cells, out);
}